// round 1
// baseline (speedup 1.0000x reference)
#include <cuda_runtime.h>
#include <math.h>

// Problem constants
#define E_TOTAL 400000
#define NNODES  12500
#define NR      128
#define HID     64
#define INDIM   256
#define OUTDIM  320
#define M0      5
#define MALL    19
#define FULLC   25
#define TILE    64      // edges per CTA
#define XP      264     // X tile pitch (floats), 16B-aligned rows
#define HP      68      // H tile pitch (floats)

// shared memory layout (floats):
//  Xs  : TILE*XP          = 16896
//  H1s : TILE*HP          = 4352
//  H2s : TILE*HP          = 4352
//  Ws  : 64*64            = 4096   (streamed weight chunk)
//  Fs  : 5*TILE*HP        = 21760  (feats_m0 per m-slice)
//  wgb : 8*128            = 1024   (per-warp wigner staging)
#define SMEM_FLOATS (TILE*XP + TILE*HP + TILE*HP + 64*64 + 5*TILE*HP + 8*128)
#define SMEM_BYTES  (SMEM_FLOATS * 4)

__device__ __forceinline__ void ln_silu_rows(float* Bs, const float* __restrict__ g,
                                             const float* __restrict__ be,
                                             int lane, int warp)
{
    // each warp normalizes 8 rows of 64; lane owns 2 adjacent columns
    float2 gv = *(const float2*)(g  + 2*lane);
    float2 bv = *(const float2*)(be + 2*lane);
    #pragma unroll
    for (int rr = 0; rr < 8; ++rr) {
        int row = warp * 8 + rr;
        float2 v = *(float2*)(Bs + row*HP + 2*lane);
        float s  = v.x + v.y;
        float s2 = v.x*v.x + v.y*v.y;
        #pragma unroll
        for (int o = 16; o > 0; o >>= 1) {
            s  += __shfl_xor_sync(0xffffffffu, s,  o);
            s2 += __shfl_xor_sync(0xffffffffu, s2, o);
        }
        float mu  = s  * (1.0f/64.0f);
        float var = s2 * (1.0f/64.0f) - mu*mu;
        float rs  = rsqrtf(fmaxf(var, 0.0f) + 1e-5f);
        float x0 = (v.x - mu) * rs * gv.x + bv.x;
        float x1 = (v.y - mu) * rs * gv.y + bv.y;
        x0 = x0 / (1.0f + __expf(-x0));
        x1 = x1 / (1.0f + __expf(-x1));
        *(float2*)(Bs + row*HP + 2*lane) = make_float2(x0, x1);
    }
}

__global__ __launch_bounds__(256, 1)
void edge_degree_kernel(
    const int*   __restrict__ species,
    const float* __restrict__ dist,
    const int*   __restrict__ senders,
    const int*   __restrict__ receivers,
    const float* __restrict__ wig,
    const float* __restrict__ env,
    const float* __restrict__ semb,
    const float* __restrict__ remb,
    const float* __restrict__ W1, const float* __restrict__ b1,
    const float* __restrict__ g1, const float* __restrict__ be1,
    const float* __restrict__ W2, const float* __restrict__ b2,
    const float* __restrict__ g2, const float* __restrict__ be2,
    const float* __restrict__ W3, const float* __restrict__ b3,
    float* __restrict__ out)
{
    extern __shared__ float sm[];
    float* Xs  = sm;
    float* H1s = Xs  + TILE*XP;
    float* H2s = H1s + TILE*HP;
    float* Ws  = H2s + TILE*HP;
    float* Fs  = Ws  + 64*64;
    float* wgb = Fs  + 5*TILE*HP;

    const int tid  = threadIdx.x;
    const int lane = tid & 31;
    const int warp = tid >> 5;     // 0..7
    const int ti   = tid >> 4;     // 0..15 (row group)
    const int tj   = tid & 15;     // 0..15 (col group)
    const int base = blockIdx.x * TILE;

    // ---------------- build X tile: [dist(128) | send_emb(64) | recv_emb(64)]
    #pragma unroll
    for (int ii = 0; ii < 8; ++ii) {
        int i = warp * 8 + ii;
        int e = base + i;
        const float4* drow = (const float4*)(dist + (size_t)e * NR);
        ((float4*)(Xs + i*XP))[lane] = drow[lane];           // 32 lanes * float4 = 128
        int snode = senders[e];
        int rnode = receivers[e];
        if (lane < 16) {
            int sp = species[snode];
            ((float4*)(Xs + i*XP + NR))[lane] = ((const float4*)(semb + sp*HID))[lane];
        } else {
            int sp = species[rnode];
            ((float4*)(Xs + i*XP + NR + HID))[lane-16] =
                ((const float4*)(remb + sp*HID))[lane-16];
        }
    }

    // ---------------- stage 1: H1 = X @ W1  (k = 256 in 4 chunks of 64)
    float4 acc0 = make_float4(0,0,0,0), acc1 = acc0, acc2 = acc0, acc3 = acc0;
    for (int kc = 0; kc < 4; ++kc) {
        __syncthreads();
        const float4* Wg4 = (const float4*)(W1 + kc * 64 * 64);
        #pragma unroll
        for (int q = 0; q < 4; ++q)
            ((float4*)Ws)[tid + 256*q] = Wg4[tid + 256*q];
        __syncthreads();
        const float* xrow0 = Xs + (4*ti + 0)*XP + kc*64;
        const float* xrow1 = Xs + (4*ti + 1)*XP + kc*64;
        const float* xrow2 = Xs + (4*ti + 2)*XP + kc*64;
        const float* xrow3 = Xs + (4*ti + 3)*XP + kc*64;
        #pragma unroll 8
        for (int k = 0; k < 64; ++k) {
            float4 b = ((const float4*)Ws)[k*16 + tj];
            float a0 = xrow0[k], a1 = xrow1[k], a2 = xrow2[k], a3 = xrow3[k];
            acc0.x += a0*b.x; acc0.y += a0*b.y; acc0.z += a0*b.z; acc0.w += a0*b.w;
            acc1.x += a1*b.x; acc1.y += a1*b.y; acc1.z += a1*b.z; acc1.w += a1*b.w;
            acc2.x += a2*b.x; acc2.y += a2*b.y; acc2.z += a2*b.z; acc2.w += a2*b.w;
            acc3.x += a3*b.x; acc3.y += a3*b.y; acc3.z += a3*b.z; acc3.w += a3*b.w;
        }
    }
    {
        float4 bv = ((const float4*)b1)[tj];
        float4 v;
        v = acc0; v.x+=bv.x; v.y+=bv.y; v.z+=bv.z; v.w+=bv.w; ((float4*)(H1s + (4*ti+0)*HP))[tj] = v;
        v = acc1; v.x+=bv.x; v.y+=bv.y; v.z+=bv.z; v.w+=bv.w; ((float4*)(H1s + (4*ti+1)*HP))[tj] = v;
        v = acc2; v.x+=bv.x; v.y+=bv.y; v.z+=bv.z; v.w+=bv.w; ((float4*)(H1s + (4*ti+2)*HP))[tj] = v;
        v = acc3; v.x+=bv.x; v.y+=bv.y; v.z+=bv.z; v.w+=bv.w; ((float4*)(H1s + (4*ti+3)*HP))[tj] = v;
    }
    __syncthreads();
    ln_silu_rows(H1s, g1, be1, lane, warp);
    __syncthreads();

    // ---------------- stage 2: H2 = H1 @ W2  (k = 64, single chunk)
    {
        #pragma unroll
        for (int q = 0; q < 4; ++q)
            ((float4*)Ws)[tid + 256*q] = ((const float4*)W2)[tid + 256*q];
        __syncthreads();
        acc0 = make_float4(0,0,0,0); acc1 = acc0; acc2 = acc0; acc3 = acc0;
        const float* xrow0 = H1s + (4*ti + 0)*HP;
        const float* xrow1 = H1s + (4*ti + 1)*HP;
        const float* xrow2 = H1s + (4*ti + 2)*HP;
        const float* xrow3 = H1s + (4*ti + 3)*HP;
        #pragma unroll 8
        for (int k = 0; k < 64; ++k) {
            float4 b = ((const float4*)Ws)[k*16 + tj];
            float a0 = xrow0[k], a1 = xrow1[k], a2 = xrow2[k], a3 = xrow3[k];
            acc0.x += a0*b.x; acc0.y += a0*b.y; acc0.z += a0*b.z; acc0.w += a0*b.w;
            acc1.x += a1*b.x; acc1.y += a1*b.y; acc1.z += a1*b.z; acc1.w += a1*b.w;
            acc2.x += a2*b.x; acc2.y += a2*b.y; acc2.z += a2*b.z; acc2.w += a2*b.w;
            acc3.x += a3*b.x; acc3.y += a3*b.y; acc3.z += a3*b.z; acc3.w += a3*b.w;
        }
        float4 bv = ((const float4*)b2)[tj];
        float4 v;
        v = acc0; v.x+=bv.x; v.y+=bv.y; v.z+=bv.z; v.w+=bv.w; ((float4*)(H2s + (4*ti+0)*HP))[tj] = v;
        v = acc1; v.x+=bv.x; v.y+=bv.y; v.z+=bv.z; v.w+=bv.w; ((float4*)(H2s + (4*ti+1)*HP))[tj] = v;
        v = acc2; v.x+=bv.x; v.y+=bv.y; v.z+=bv.z; v.w+=bv.w; ((float4*)(H2s + (4*ti+2)*HP))[tj] = v;
        v = acc3; v.x+=bv.x; v.y+=bv.y; v.z+=bv.z; v.w+=bv.w; ((float4*)(H2s + (4*ti+3)*HP))[tj] = v;
    }
    __syncthreads();
    ln_silu_rows(H2s, g2, be2, lane, warp);

    // ---------------- stage 3: F_m = H2 @ W3[:, m*64:(m+1)*64] + b3, m = 0..4
    for (int m = 0; m < 5; ++m) {
        __syncthreads();   // Ws free of readers; H2s ready (first iter)
        #pragma unroll
        for (int q = 0; q < 4; ++q) {
            int lin = tid + 256*q;
            int k   = lin >> 4;
            int j4  = lin & 15;
            ((float4*)Ws)[lin] = ((const float4*)W3)[k*80 + m*16 + j4];
        }
        __syncthreads();
        acc0 = make_float4(0,0,0,0); acc1 = acc0; acc2 = acc0; acc3 = acc0;
        const float* xrow0 = H2s + (4*ti + 0)*HP;
        const float* xrow1 = H2s + (4*ti + 1)*HP;
        const float* xrow2 = H2s + (4*ti + 2)*HP;
        const float* xrow3 = H2s + (4*ti + 3)*HP;
        #pragma unroll 8
        for (int k = 0; k < 64; ++k) {
            float4 b = ((const float4*)Ws)[k*16 + tj];
            float a0 = xrow0[k], a1 = xrow1[k], a2 = xrow2[k], a3 = xrow3[k];
            acc0.x += a0*b.x; acc0.y += a0*b.y; acc0.z += a0*b.z; acc0.w += a0*b.w;
            acc1.x += a1*b.x; acc1.y += a1*b.y; acc1.z += a1*b.z; acc1.w += a1*b.w;
            acc2.x += a2*b.x; acc2.y += a2*b.y; acc2.z += a2*b.z; acc2.w += a2*b.w;
            acc3.x += a3*b.x; acc3.y += a3*b.y; acc3.z += a3*b.z; acc3.w += a3*b.w;
        }
        float4 bv = ((const float4*)b3)[m*16 + tj];
        float4 v;
        v = acc0; v.x+=bv.x; v.y+=bv.y; v.z+=bv.z; v.w+=bv.w; ((float4*)(Fs + (m*64 + 4*ti+0)*HP))[tj] = v;
        v = acc1; v.x+=bv.x; v.y+=bv.y; v.z+=bv.z; v.w+=bv.w; ((float4*)(Fs + (m*64 + 4*ti+1)*HP))[tj] = v;
        v = acc2; v.x+=bv.x; v.y+=bv.y; v.z+=bv.z; v.w+=bv.w; ((float4*)(Fs + (m*64 + 4*ti+2)*HP))[tj] = v;
        v = acc3; v.x+=bv.x; v.y+=bv.y; v.z+=bv.z; v.w+=bv.w; ((float4*)(Fs + (m*64 + 4*ti+3)*HP))[tj] = v;
    }
    __syncthreads();

    // ---------------- wigner rotation + scatter (warp = 8 edges, lane = 2 cols)
    float* wb = wgb + warp * 128;
    for (int ii = 0; ii < 8; ++ii) {
        int i = warp * 8 + ii;
        int e = base + i;
        const float* wr = wig + (size_t)e * (FULLC * MALL);
        // cooperative load of the 125 needed coefficients (m < 5 of each row f)
        #pragma unroll
        for (int t = 0; t < 4; ++t) {
            int lin = lane + 32*t;
            if (lin < 125) {
                int f = lin / 5;
                int m = lin - 5*f;
                wb[lin] = wr[f*MALL + m];
            }
        }
        __syncwarp();

        float sc = env[e] * 0.2f;             // fold 1/RESCALE
        int rnode = receivers[e];
        float2 fm0 = *(float2*)(Fs + (0*64 + i)*HP + 2*lane);
        float2 fm1 = *(float2*)(Fs + (1*64 + i)*HP + 2*lane);
        float2 fm2 = *(float2*)(Fs + (2*64 + i)*HP + 2*lane);
        float2 fm3 = *(float2*)(Fs + (3*64 + i)*HP + 2*lane);
        float2 fm4 = *(float2*)(Fs + (4*64 + i)*HP + 2*lane);
        float* ob = out + (size_t)rnode * (FULLC * HID) + 2*lane;

        #pragma unroll
        for (int f = 0; f < FULLC; ++f) {
            float w0 = wb[f*5+0], w1 = wb[f*5+1], w2 = wb[f*5+2],
                  w3 = wb[f*5+3], w4 = wb[f*5+4];
            float r0 = w0*fm0.x + w1*fm1.x + w2*fm2.x + w3*fm3.x + w4*fm4.x;
            float r1 = w0*fm0.y + w1*fm1.y + w2*fm2.y + w3*fm3.y + w4*fm4.y;
            atomicAdd(ob + f*HID,     r0 * sc);
            atomicAdd(ob + f*HID + 1, r1 * sc);
        }
        __syncwarp();  // wb reused next edge
    }
}

extern "C" void kernel_launch(void* const* d_in, const int* in_sizes, int n_in,
                              void* d_out, int out_size)
{
    const int*   species   = (const int*)  d_in[0];
    const float* dist      = (const float*)d_in[1];
    const int*   senders   = (const int*)  d_in[2];
    const int*   receivers = (const int*)  d_in[3];
    const float* wig       = (const float*)d_in[4];
    const float* env       = (const float*)d_in[5];
    const float* semb      = (const float*)d_in[6];
    const float* remb      = (const float*)d_in[7];
    const float* W1  = (const float*)d_in[8];
    const float* b1  = (const float*)d_in[9];
    const float* g1  = (const float*)d_in[10];
    const float* be1 = (const float*)d_in[11];
    const float* W2  = (const float*)d_in[12];
    const float* b2  = (const float*)d_in[13];
    const float* g2  = (const float*)d_in[14];
    const float* be2 = (const float*)d_in[15];
    const float* W3  = (const float*)d_in[16];
    const float* b3  = (const float*)d_in[17];
    float* out = (float*)d_out;

    cudaFuncSetAttribute(edge_degree_kernel,
                         cudaFuncAttributeMaxDynamicSharedMemorySize, SMEM_BYTES);
    cudaMemsetAsync(d_out, 0, (size_t)out_size * sizeof(float), 0);
    edge_degree_kernel<<<E_TOTAL / TILE, 256, SMEM_BYTES>>>(
        species, dist, senders, receivers, wig, env, semb, remb,
        W1, b1, g1, be1, W2, b2, g2, be2, W3, b3, out);
}

// round 2
// speedup vs baseline: 1.0680x; 1.0680x over previous
#include <cuda_runtime.h>
#include <math.h>

#define E_TOTAL 400000
#define NNODES  12500
#define T1      128     // edges per CTA, kernel 1
#define T2      64      // edges per CTA, kernel 2
#define PH      68      // smem row pitch (floats), %8==4 -> only 2-way conflict on a-loads
#define FULLC   25
#define MALL    19

typedef unsigned long long ull;

// F scratch: [E][5*64] = 512 MB device global (sanctioned scratch, no alloc in launch)
__device__ float F_buf[(size_t)E_TOTAL * 320];

__device__ __forceinline__ ull pack2(float x) {
    ull r; asm("mov.b64 %0,{%1,%1};" : "=l"(r) : "f"(x)); return r;
}
__device__ __forceinline__ void fma2(ull& d, ull a, ull b) {
    asm("fma.rn.f32x2 %0,%1,%2,%0;" : "+l"(d) : "l"(a), "l"(b));
}
__device__ __forceinline__ float2 unpk(ull v) {
    float2 o; asm("mov.b64 {%0,%1},%2;" : "=f"(o.x), "=f"(o.y) : "l"(v)); return o;
}

// 128x64 * 64x64 accumulate: thread tile 4 rows x 8 cols (4 packed pairs)
__device__ __forceinline__ void gemm64(const float* __restrict__ As,
                                       const ull*  __restrict__ Wp,
                                       int row0, int cj, ull acc[16])
{
    const float* a0 = As + (row0 + 0) * PH;
    const float* a1 = As + (row0 + 1) * PH;
    const float* a2 = As + (row0 + 2) * PH;
    const float* a3 = As + (row0 + 3) * PH;
    #pragma unroll 2
    for (int k4 = 0; k4 < 16; ++k4) {
        float4 v0 = *(const float4*)(a0 + 4 * k4);
        float4 v1 = *(const float4*)(a1 + 4 * k4);
        float4 v2 = *(const float4*)(a2 + 4 * k4);
        float4 v3 = *(const float4*)(a3 + 4 * k4);
        float a0a[4] = {v0.x, v0.y, v0.z, v0.w};
        float a1a[4] = {v1.x, v1.y, v1.z, v1.w};
        float a2a[4] = {v2.x, v2.y, v2.z, v2.w};
        float a3a[4] = {v3.x, v3.y, v3.z, v3.w};
        #pragma unroll
        for (int kk = 0; kk < 4; ++kk) {
            int k = 4 * k4 + kk;
            ulonglong2 bA = *(const ulonglong2*)(Wp + k * 32 + cj * 4);
            ulonglong2 bB = *(const ulonglong2*)(Wp + k * 32 + cj * 4 + 2);
            ull p;
            p = pack2(a0a[kk]); fma2(acc[0], p, bA.x); fma2(acc[1], p, bA.y); fma2(acc[2],  p, bB.x); fma2(acc[3],  p, bB.y);
            p = pack2(a1a[kk]); fma2(acc[4], p, bA.x); fma2(acc[5], p, bA.y); fma2(acc[6],  p, bB.x); fma2(acc[7],  p, bB.y);
            p = pack2(a2a[kk]); fma2(acc[8], p, bA.x); fma2(acc[9], p, bA.y); fma2(acc[10], p, bB.x); fma2(acc[11], p, bB.y);
            p = pack2(a3a[kk]); fma2(acc[12],p, bA.x); fma2(acc[13],p, bA.y); fma2(acc[14], p, bB.x); fma2(acc[15], p, bB.y);
        }
    }
}

// store acc (+bias) to smem H at pitch PH
__device__ __forceinline__ void store_acc_smem(float* __restrict__ H, int row0, int cj,
                                               const ull acc[16], float4 bl, float4 bh)
{
    #pragma unroll
    for (int r = 0; r < 4; ++r) {
        float2 e0 = unpk(acc[4*r+0]); float2 e1 = unpk(acc[4*r+1]);
        float2 e2 = unpk(acc[4*r+2]); float2 e3 = unpk(acc[4*r+3]);
        float* p = H + (row0 + r) * PH + cj * 8;
        *(float4*)(p)     = make_float4(e0.x + bl.x, e0.y + bl.y, e1.x + bl.z, e1.y + bl.w);
        *(float4*)(p + 4) = make_float4(e2.x + bh.x, e2.y + bh.y, e3.x + bh.z, e3.y + bh.w);
    }
}

__device__ __forceinline__ void ln_silu(float* __restrict__ Bs,
                                        const float* __restrict__ g,
                                        const float* __restrict__ be,
                                        int lane, int warp)
{
    float2 gv = *(const float2*)(g  + 2 * lane);
    float2 bv = *(const float2*)(be + 2 * lane);
    #pragma unroll
    for (int rr = 0; rr < 16; ++rr) {
        int row = warp * 16 + rr;
        float2 v = *(float2*)(Bs + row * PH + 2 * lane);
        float s  = v.x + v.y;
        float s2 = v.x * v.x + v.y * v.y;
        #pragma unroll
        for (int o = 16; o > 0; o >>= 1) {
            s  += __shfl_xor_sync(0xffffffffu, s,  o);
            s2 += __shfl_xor_sync(0xffffffffu, s2, o);
        }
        float mu  = s * (1.0f / 64.0f);
        float var = s2 * (1.0f / 64.0f) - mu * mu;
        float rs  = rsqrtf(fmaxf(var, 0.0f) + 1e-5f);
        float x0 = (v.x - mu) * rs * gv.x + bv.x;
        float x1 = (v.y - mu) * rs * gv.y + bv.y;
        x0 = x0 / (1.0f + __expf(-x0));
        x1 = x1 / (1.0f + __expf(-x1));
        *(float2*)(Bs + row * PH + 2 * lane) = make_float2(x0, x1);
    }
}

// smem: Xc(128*68) | H1(128*68) | Ws(64*64) | spS(128) spR(128)
#define SM1_FLOATS (T1 * PH + T1 * PH + 64 * 64 + 64)
#define SM1_BYTES  (SM1_FLOATS * 4 + 1024)

__global__ __launch_bounds__(256, 2)
void mlp_kernel(const int*   __restrict__ species,
                const float* __restrict__ dist,
                const int*   __restrict__ senders,
                const int*   __restrict__ receivers,
                const float* __restrict__ semb,
                const float* __restrict__ remb,
                const float* __restrict__ W1, const float* __restrict__ b1,
                const float* __restrict__ g1, const float* __restrict__ be1,
                const float* __restrict__ W2, const float* __restrict__ b2,
                const float* __restrict__ g2, const float* __restrict__ be2,
                const float* __restrict__ W3, const float* __restrict__ b3)
{
    extern __shared__ float sm[];
    float* Xc = sm;                     // also H2 later
    float* H1 = Xc + T1 * PH;
    float* Ws = H1 + T1 * PH;
    int*   spS = (int*)(Ws + 64 * 64 + 64);
    int*   spR = spS + T1;

    const int tid  = threadIdx.x;
    const int lane = tid & 31;
    const int warp = tid >> 5;
    const int ri   = tid >> 3;      // 0..31 -> rows 4ri..4ri+3
    const int cj   = tid & 7;       // 0..7  -> cols 8cj..8cj+7
    const int row0 = 4 * ri;
    const int base = blockIdx.x * T1;

    if (tid < T1) {
        spS[tid] = species[senders[base + tid]];
        spR[tid] = species[receivers[base + tid]];
    }

    ull acc[16];
    #pragma unroll
    for (int i = 0; i < 16; ++i) acc[i] = 0ull;

    // ------------- stage 1: H1 = X @ W1 (k in 4 chunks of 64)
    for (int kc = 0; kc < 4; ++kc) {
        __syncthreads();
        // load Ws chunk of W1
        #pragma unroll
        for (int q = 0; q < 4; ++q) {
            int lin = tid + 256 * q;          // 1024 float4
            int k = lin >> 4, c4 = lin & 15;
            ((float4*)Ws)[lin] = ((const float4*)W1)[(kc * 64 + k) * 16 + c4];
        }
        // load X chunk
        #pragma unroll
        for (int q = 0; q < 8; ++q) {
            int lin = tid + 256 * q;          // 2048 float4 = 128 rows x 16
            int row = lin >> 4, c4 = lin & 15;
            float4 v;
            if (kc < 2) {
                v = ((const float4*)dist)[(size_t)(base + row) * 32 + kc * 16 + c4];
            } else if (kc == 2) {
                v = ((const float4*)semb)[spS[row] * 16 + c4];
            } else {
                v = ((const float4*)remb)[spR[row] * 16 + c4];
            }
            *(float4*)(Xc + row * PH + c4 * 4) = v;
        }
        __syncthreads();
        gemm64(Xc, (const ull*)Ws, row0, cj, acc);
    }
    {
        float4 bl = ((const float4*)b1)[cj * 2];
        float4 bh = ((const float4*)b1)[cj * 2 + 1];
        __syncthreads();
        store_acc_smem(H1, row0, cj, acc, bl, bh);
    }
    __syncthreads();
    ln_silu(H1, g1, be1, lane, warp);
    __syncthreads();

    // ------------- stage 2: H2 = H1 @ W2 (H2 aliases Xc)
    #pragma unroll
    for (int q = 0; q < 4; ++q) {
        int lin = tid + 256 * q;
        ((float4*)Ws)[lin] = ((const float4*)W2)[lin];
    }
    __syncthreads();
    #pragma unroll
    for (int i = 0; i < 16; ++i) acc[i] = 0ull;
    gemm64(H1, (const ull*)Ws, row0, cj, acc);
    {
        float4 bl = ((const float4*)b2)[cj * 2];
        float4 bh = ((const float4*)b2)[cj * 2 + 1];
        __syncthreads();                       // Xc readers done
        store_acc_smem(Xc, row0, cj, acc, bl, bh);
    }
    __syncthreads();
    ln_silu(Xc, g2, be2, lane, warp);

    // ------------- stage 3: F_m = H2 @ W3[:, 64m:64m+64] + b3, STG to F_buf
    for (int m = 0; m < 5; ++m) {
        __syncthreads();
        #pragma unroll
        for (int q = 0; q < 4; ++q) {
            int lin = tid + 256 * q;
            int k = lin >> 4, c4 = lin & 15;
            ((float4*)Ws)[lin] = ((const float4*)W3)[k * 80 + m * 16 + c4];
        }
        __syncthreads();
        #pragma unroll
        for (int i = 0; i < 16; ++i) acc[i] = 0ull;
        gemm64(Xc, (const ull*)Ws, row0, cj, acc);

        float4 bl = ((const float4*)b3)[m * 16 + cj * 2];
        float4 bh = ((const float4*)b3)[m * 16 + cj * 2 + 1];
        #pragma unroll
        for (int r = 0; r < 4; ++r) {
            float2 e0 = unpk(acc[4*r+0]); float2 e1 = unpk(acc[4*r+1]);
            float2 e2 = unpk(acc[4*r+2]); float2 e3 = unpk(acc[4*r+3]);
            float* p = F_buf + (size_t)(base + row0 + r) * 320 + m * 64 + cj * 8;
            *(float4*)(p)     = make_float4(e0.x + bl.x, e0.y + bl.y, e1.x + bl.z, e1.y + bl.w);
            *(float4*)(p + 4) = make_float4(e2.x + bh.x, e2.y + bh.y, e3.x + bh.z, e3.y + bh.w);
        }
    }
}

// ---------------- kernel 2: wigner rotation + scatter-add
__global__ __launch_bounds__(256)
void wigner_kernel(const int*   __restrict__ receivers,
                   const float* __restrict__ wig,
                   const float* __restrict__ env,
                   float* __restrict__ out)
{
    __shared__ float wgb[8 * 128];
    const int tid  = threadIdx.x;
    const int lane = tid & 31;
    const int warp = tid >> 5;
    const int base = blockIdx.x * T2;
    float* wb = wgb + warp * 128;

    for (int ii = 0; ii < 8; ++ii) {
        int e = base + warp * 8 + ii;
        float sc = env[e] * 0.2f;              // fold 1/RESCALE
        const float* wr = wig + (size_t)e * (FULLC * MALL);
        // stage 125 coeffs, pre-scaled by env/5
        #pragma unroll
        for (int t = 0; t < 4; ++t) {
            int lin = lane + 32 * t;
            if (lin < 125) {
                int f = lin / 5;
                int m = lin - 5 * f;
                wb[lin] = wr[f * MALL + m] * sc;
            }
        }
        __syncwarp();

        const ull* fp = (const ull*)(F_buf + (size_t)e * 320 + 2 * lane);
        ull fm0 = fp[0], fm1 = fp[32], fm2 = fp[64], fm3 = fp[96], fm4 = fp[128];
        int rnode = receivers[e];
        float* ob = out + (size_t)rnode * 1600 + 2 * lane;

        #pragma unroll
        for (int f = 0; f < FULLC; ++f) {
            ull r = 0ull;
            fma2(r, pack2(wb[f*5+0]), fm0);
            fma2(r, pack2(wb[f*5+1]), fm1);
            fma2(r, pack2(wb[f*5+2]), fm2);
            fma2(r, pack2(wb[f*5+3]), fm3);
            fma2(r, pack2(wb[f*5+4]), fm4);
            float2 rv = unpk(r);
            asm volatile("red.global.add.v2.f32 [%0], {%1, %2};"
                         :: "l"(ob + f * 64), "f"(rv.x), "f"(rv.y) : "memory");
        }
        __syncwarp();
    }
}

extern "C" void kernel_launch(void* const* d_in, const int* in_sizes, int n_in,
                              void* d_out, int out_size)
{
    const int*   species   = (const int*)  d_in[0];
    const float* dist      = (const float*)d_in[1];
    const int*   senders   = (const int*)  d_in[2];
    const int*   receivers = (const int*)  d_in[3];
    const float* wig       = (const float*)d_in[4];
    const float* env       = (const float*)d_in[5];
    const float* semb      = (const float*)d_in[6];
    const float* remb      = (const float*)d_in[7];
    const float* W1  = (const float*)d_in[8];
    const float* b1  = (const float*)d_in[9];
    const float* g1  = (const float*)d_in[10];
    const float* be1 = (const float*)d_in[11];
    const float* W2  = (const float*)d_in[12];
    const float* b2  = (const float*)d_in[13];
    const float* g2  = (const float*)d_in[14];
    const float* be2 = (const float*)d_in[15];
    const float* W3  = (const float*)d_in[16];
    const float* b3  = (const float*)d_in[17];
    float* out = (float*)d_out;

    cudaFuncSetAttribute(mlp_kernel,
                         cudaFuncAttributeMaxDynamicSharedMemorySize, SM1_BYTES);
    cudaMemsetAsync(d_out, 0, (size_t)out_size * sizeof(float), 0);
    mlp_kernel<<<E_TOTAL / T1, 256, SM1_BYTES>>>(
        species, dist, senders, receivers, semb, remb,
        W1, b1, g1, be1, W2, b2, g2, be2, W3, b3);
    wigner_kernel<<<E_TOTAL / T2, 256>>>(receivers, wig, env, out);
}

// round 3
// speedup vs baseline: 1.2510x; 1.1713x over previous
#include <cuda_runtime.h>
#include <math.h>

#define E_TOTAL 400000
#define NNODES  12500
#define T1      128     // edges per CTA, kernel 1
#define PH      68      // smem row pitch (floats)
#define FULLC   25
#define MALL    19
#define NSPEC   90

typedef unsigned long long ull;

// scratch (static device globals; no allocation in kernel_launch)
__device__ float F_buf[(size_t)E_TOTAL * 320];   // MLP output per edge
__device__ int   d_cnt[NNODES];
__device__ int   d_cur[NNODES];
__device__ int   d_offs[NNODES + 1];
__device__ int   d_eids[E_TOTAL];
__device__ float SPb[NSPEC * 64];                // semb @ W1[128:192] + b1
__device__ float RPb[NSPEC * 64];                // remb @ W1[192:256]

__device__ __forceinline__ ull pack2(float x) {
    ull r; asm("mov.b64 %0,{%1,%1};" : "=l"(r) : "f"(x)); return r;
}
__device__ __forceinline__ ull pack2xy(float x, float y) {
    ull r; asm("mov.b64 %0,{%1,%2};" : "=l"(r) : "f"(x), "f"(y)); return r;
}
__device__ __forceinline__ void fma2(ull& d, ull a, ull b) {
    asm("fma.rn.f32x2 %0,%1,%2,%0;" : "+l"(d) : "l"(a), "l"(b));
}
__device__ __forceinline__ float2 unpk(ull v) {
    float2 o; asm("mov.b64 {%0,%1},%2;" : "=f"(o.x), "=f"(o.y) : "l"(v)); return o;
}

// ---------------------------------------------------------------- CSR build
__global__ void zero_kernel() {
    int i = blockIdx.x * blockDim.x + threadIdx.x;
    if (i < NNODES) { d_cnt[i] = 0; d_cur[i] = 0; }
}
__global__ void hist_kernel(const int* __restrict__ receivers) {
    int e = blockIdx.x * blockDim.x + threadIdx.x;
    if (e < E_TOTAL) atomicAdd(&d_cnt[receivers[e]], 1);
}
__global__ void scan_kernel() {
    __shared__ int s[1024];
    const int CH = (NNODES + 1023) / 1024;   // 13
    int t = threadIdx.x;
    int base = t * CH;
    int loc[CH];
    int sum = 0;
    #pragma unroll
    for (int i = 0; i < CH; ++i) {
        int v = (base + i < NNODES) ? d_cnt[base + i] : 0;
        loc[i] = sum; sum += v;
    }
    s[t] = sum;
    __syncthreads();
    for (int off = 1; off < 1024; off <<= 1) {
        int v = s[t];
        int u = (t >= off) ? s[t - off] : 0;
        __syncthreads();
        s[t] = v + u;
        __syncthreads();
    }
    int excl = (t > 0) ? s[t - 1] : 0;
    #pragma unroll
    for (int i = 0; i < CH; ++i)
        if (base + i < NNODES) d_offs[base + i] = excl + loc[i];
    if (t == 1023) d_offs[NNODES] = s[1023];
}
__global__ void fill_kernel(const int* __restrict__ receivers) {
    int e = blockIdx.x * blockDim.x + threadIdx.x;
    if (e < E_TOTAL) {
        int r = receivers[e];
        int pos = atomicAdd(&d_cur[r], 1);
        d_eids[d_offs[r] + pos] = e;
    }
}

// -------------------------------------------- species projection precompute
__global__ void species_kernel(const float* __restrict__ semb,
                               const float* __restrict__ remb,
                               const float* __restrict__ W1,
                               const float* __restrict__ b1)
{
    int s = blockIdx.x;        // 0..89
    int c = threadIdx.x;       // 0..63
    float sp = b1[c], rp = 0.0f;
    #pragma unroll 8
    for (int k = 0; k < 64; ++k) {
        sp += semb[s * 64 + k] * W1[(128 + k) * 64 + c];
        rp += remb[s * 64 + k] * W1[(192 + k) * 64 + c];
    }
    SPb[s * 64 + c] = sp;
    RPb[s * 64 + c] = rp;
}

// ---------------------------------------------------------------- MLP GEMM
__device__ __forceinline__ void gemm64(const float* __restrict__ As,
                                       const ull*  __restrict__ Wp,
                                       int row0, int cj, ull acc[16])
{
    const float* a0 = As + (row0 + 0) * PH;
    const float* a1 = As + (row0 + 1) * PH;
    const float* a2 = As + (row0 + 2) * PH;
    const float* a3 = As + (row0 + 3) * PH;
    #pragma unroll 2
    for (int k4 = 0; k4 < 16; ++k4) {
        float4 v0 = *(const float4*)(a0 + 4 * k4);
        float4 v1 = *(const float4*)(a1 + 4 * k4);
        float4 v2 = *(const float4*)(a2 + 4 * k4);
        float4 v3 = *(const float4*)(a3 + 4 * k4);
        float a0a[4] = {v0.x, v0.y, v0.z, v0.w};
        float a1a[4] = {v1.x, v1.y, v1.z, v1.w};
        float a2a[4] = {v2.x, v2.y, v2.z, v2.w};
        float a3a[4] = {v3.x, v3.y, v3.z, v3.w};
        #pragma unroll
        for (int kk = 0; kk < 4; ++kk) {
            int k = 4 * k4 + kk;
            ulonglong2 bA = *(const ulonglong2*)(Wp + k * 32 + cj * 4);
            ulonglong2 bB = *(const ulonglong2*)(Wp + k * 32 + cj * 4 + 2);
            ull p;
            p = pack2(a0a[kk]); fma2(acc[0], p, bA.x); fma2(acc[1], p, bA.y); fma2(acc[2],  p, bB.x); fma2(acc[3],  p, bB.y);
            p = pack2(a1a[kk]); fma2(acc[4], p, bA.x); fma2(acc[5], p, bA.y); fma2(acc[6],  p, bB.x); fma2(acc[7],  p, bB.y);
            p = pack2(a2a[kk]); fma2(acc[8], p, bA.x); fma2(acc[9], p, bA.y); fma2(acc[10], p, bB.x); fma2(acc[11], p, bB.y);
            p = pack2(a3a[kk]); fma2(acc[12],p, bA.x); fma2(acc[13],p, bA.y); fma2(acc[14], p, bB.x); fma2(acc[15], p, bB.y);
        }
    }
}

__device__ __forceinline__ void store_acc_smem(float* __restrict__ H, int row0, int cj,
                                               const ull acc[16], float4 bl, float4 bh)
{
    #pragma unroll
    for (int r = 0; r < 4; ++r) {
        float2 e0 = unpk(acc[4*r+0]); float2 e1 = unpk(acc[4*r+1]);
        float2 e2 = unpk(acc[4*r+2]); float2 e3 = unpk(acc[4*r+3]);
        float* p = H + (row0 + r) * PH + cj * 8;
        *(float4*)(p)     = make_float4(e0.x + bl.x, e0.y + bl.y, e1.x + bl.z, e1.y + bl.w);
        *(float4*)(p + 4) = make_float4(e2.x + bh.x, e2.y + bh.y, e3.x + bh.z, e3.y + bh.w);
    }
}

__device__ __forceinline__ void ln_silu(float* __restrict__ Bs,
                                        const float* __restrict__ g,
                                        const float* __restrict__ be,
                                        int lane, int warp)
{
    float2 gv = *(const float2*)(g  + 2 * lane);
    float2 bv = *(const float2*)(be + 2 * lane);
    #pragma unroll
    for (int rr = 0; rr < 16; ++rr) {
        int row = warp * 16 + rr;
        float2 v = *(float2*)(Bs + row * PH + 2 * lane);
        float s  = v.x + v.y;
        float s2 = v.x * v.x + v.y * v.y;
        #pragma unroll
        for (int o = 16; o > 0; o >>= 1) {
            s  += __shfl_xor_sync(0xffffffffu, s,  o);
            s2 += __shfl_xor_sync(0xffffffffu, s2, o);
        }
        float mu  = s * (1.0f / 64.0f);
        float var = s2 * (1.0f / 64.0f) - mu * mu;
        float rs  = rsqrtf(fmaxf(var, 0.0f) + 1e-5f);
        float x0 = (v.x - mu) * rs * gv.x + bv.x;
        float x1 = (v.y - mu) * rs * gv.y + bv.y;
        x0 = x0 / (1.0f + __expf(-x0));
        x1 = x1 / (1.0f + __expf(-x1));
        *(float2*)(Bs + row * PH + 2 * lane) = make_float2(x0, x1);
    }
}

#define SM1_FLOATS (T1 * PH + T1 * PH + 64 * 64 + 64)
#define SM1_BYTES  (SM1_FLOATS * 4 + 1024)

__global__ __launch_bounds__(256, 2)
void mlp_kernel(const int*   __restrict__ species,
                const float* __restrict__ dist,
                const int*   __restrict__ senders,
                const int*   __restrict__ receivers,
                const float* __restrict__ W1,
                const float* __restrict__ g1, const float* __restrict__ be1,
                const float* __restrict__ W2, const float* __restrict__ b2,
                const float* __restrict__ g2, const float* __restrict__ be2,
                const float* __restrict__ W3, const float* __restrict__ b3)
{
    extern __shared__ float sm[];
    float* Xc = sm;                     // aliased as H2 later
    float* H1 = Xc + T1 * PH;
    float* Ws = H1 + T1 * PH;
    int*   spS = (int*)(Ws + 64 * 64 + 64);
    int*   spR = spS + T1;

    const int tid  = threadIdx.x;
    const int lane = tid & 31;
    const int warp = tid >> 5;
    const int ri   = tid >> 3;
    const int cj   = tid & 7;
    const int row0 = 4 * ri;
    const int base = blockIdx.x * T1;

    if (tid < T1) {
        spS[tid] = species[senders[base + tid]];
        spR[tid] = species[receivers[base + tid]];
    }
    __syncthreads();

    // ---- stage 1 acc init from precomputed species projections (incl. b1)
    ull acc[16];
    #pragma unroll
    for (int r = 0; r < 4; ++r) {
        int row = row0 + r;
        int ss = spS[row], sr = spR[row];
        float4 u0 = ((const float4*)SPb)[ss * 16 + cj * 2];
        float4 u1 = ((const float4*)SPb)[ss * 16 + cj * 2 + 1];
        float4 v0 = ((const float4*)RPb)[sr * 16 + cj * 2];
        float4 v1 = ((const float4*)RPb)[sr * 16 + cj * 2 + 1];
        acc[4*r+0] = pack2xy(u0.x + v0.x, u0.y + v0.y);
        acc[4*r+1] = pack2xy(u0.z + v0.z, u0.w + v0.w);
        acc[4*r+2] = pack2xy(u1.x + v1.x, u1.y + v1.y);
        acc[4*r+3] = pack2xy(u1.z + v1.z, u1.w + v1.w);
    }

    // ---- stage 1: += dist @ W1[0:128] (2 chunks of 64)
    for (int kc = 0; kc < 2; ++kc) {
        __syncthreads();
        #pragma unroll
        for (int q = 0; q < 4; ++q) {
            int lin = tid + 256 * q;
            int k = lin >> 4, c4 = lin & 15;
            ((float4*)Ws)[lin] = ((const float4*)W1)[(kc * 64 + k) * 16 + c4];
        }
        #pragma unroll
        for (int q = 0; q < 8; ++q) {
            int lin = tid + 256 * q;
            int row = lin >> 4, c4 = lin & 15;
            float4 v = ((const float4*)dist)[(size_t)(base + row) * 32 + kc * 16 + c4];
            *(float4*)(Xc + row * PH + c4 * 4) = v;
        }
        __syncthreads();
        gemm64(Xc, (const ull*)Ws, row0, cj, acc);
    }
    {
        float4 z = make_float4(0, 0, 0, 0);
        __syncthreads();
        store_acc_smem(H1, row0, cj, acc, z, z);
    }
    __syncthreads();
    ln_silu(H1, g1, be1, lane, warp);
    __syncthreads();

    // ---- stage 2: H2 = H1 @ W2 (H2 aliases Xc)
    #pragma unroll
    for (int q = 0; q < 4; ++q)
        ((float4*)Ws)[tid + 256 * q] = ((const float4*)W2)[tid + 256 * q];
    __syncthreads();
    #pragma unroll
    for (int i = 0; i < 16; ++i) acc[i] = 0ull;
    gemm64(H1, (const ull*)Ws, row0, cj, acc);
    {
        float4 bl = ((const float4*)b2)[cj * 2];
        float4 bh = ((const float4*)b2)[cj * 2 + 1];
        __syncthreads();
        store_acc_smem(Xc, row0, cj, acc, bl, bh);
    }
    __syncthreads();
    ln_silu(Xc, g2, be2, lane, warp);

    // ---- stage 3: F_m = H2 @ W3[:, 64m:64m+64] + b3 -> F_buf
    for (int m = 0; m < 5; ++m) {
        __syncthreads();
        #pragma unroll
        for (int q = 0; q < 4; ++q) {
            int lin = tid + 256 * q;
            int k = lin >> 4, c4 = lin & 15;
            ((float4*)Ws)[lin] = ((const float4*)W3)[k * 80 + m * 16 + c4];
        }
        __syncthreads();
        #pragma unroll
        for (int i = 0; i < 16; ++i) acc[i] = 0ull;
        gemm64(Xc, (const ull*)Ws, row0, cj, acc);

        float4 bl = ((const float4*)b3)[m * 16 + cj * 2];
        float4 bh = ((const float4*)b3)[m * 16 + cj * 2 + 1];
        #pragma unroll
        for (int r = 0; r < 4; ++r) {
            float2 e0 = unpk(acc[4*r+0]); float2 e1 = unpk(acc[4*r+1]);
            float2 e2 = unpk(acc[4*r+2]); float2 e3 = unpk(acc[4*r+3]);
            float* p = F_buf + (size_t)(base + row0 + r) * 320 + m * 64 + cj * 8;
            *(float4*)(p)     = make_float4(e0.x + bl.x, e0.y + bl.y, e1.x + bl.z, e1.y + bl.w);
            *(float4*)(p + 4) = make_float4(e2.x + bh.x, e2.y + bh.y, e3.x + bh.z, e3.y + bh.w);
        }
    }
}

// --------------------------------- kernel 2: gather per node, no atomics
__global__ __launch_bounds__(256)
void wigner_gather(const float* __restrict__ wig,
                   const float* __restrict__ env,
                   float* __restrict__ out)
{
    __shared__ ull wbp[8][25 * 8];     // per-warp packed coeffs, stride 8 per f
    const int tid  = threadIdx.x;
    const int lane = tid & 31;
    const int warp = tid >> 5;
    const int node = blockIdx.x * 8 + warp;
    if (node >= NNODES) return;

    ull acc[FULLC];
    #pragma unroll
    for (int f = 0; f < FULLC; ++f) acc[f] = 0ull;

    const int beg = d_offs[node];
    const int end = d_offs[node + 1];
    ull* wp = wbp[warp];

    for (int idx = beg; idx < end; ++idx) {
        int e = d_eids[idx];
        float sc = env[e] * 0.2f;      // fold 1/RESCALE
        const float* wr = wig + (size_t)e * (FULLC * MALL);
        #pragma unroll
        for (int t = 0; t < 4; ++t) {
            int lin = lane + 32 * t;
            if (lin < 125) {
                int f = lin / 5;
                int m = lin - 5 * f;
                wp[f * 8 + m] = pack2(wr[f * MALL + m] * sc);
            }
        }
        __syncwarp();

        const ull* fp = (const ull*)(F_buf + (size_t)e * 320 + 2 * lane);
        ull fm0 = fp[0], fm1 = fp[32], fm2 = fp[64], fm3 = fp[96], fm4 = fp[128];

        #pragma unroll
        for (int f = 0; f < FULLC; ++f) {
            ulonglong2 wA = *(const ulonglong2*)(wp + f * 8);
            ulonglong2 wB = *(const ulonglong2*)(wp + f * 8 + 2);
            ull w4 = wp[f * 8 + 4];
            ull r = acc[f];
            fma2(r, wA.x, fm0);
            fma2(r, wA.y, fm1);
            fma2(r, wB.x, fm2);
            fma2(r, wB.y, fm3);
            fma2(r, w4,   fm4);
            acc[f] = r;
        }
        __syncwarp();
    }

    float* ob = out + (size_t)node * 1600 + 2 * lane;
    #pragma unroll
    for (int f = 0; f < FULLC; ++f) {
        float2 rv = unpk(acc[f]);
        *(float2*)(ob + f * 64) = rv;
    }
}

extern "C" void kernel_launch(void* const* d_in, const int* in_sizes, int n_in,
                              void* d_out, int out_size)
{
    const int*   species   = (const int*)  d_in[0];
    const float* dist      = (const float*)d_in[1];
    const int*   senders   = (const int*)  d_in[2];
    const int*   receivers = (const int*)  d_in[3];
    const float* wig       = (const float*)d_in[4];
    const float* env       = (const float*)d_in[5];
    const float* semb      = (const float*)d_in[6];
    const float* remb      = (const float*)d_in[7];
    const float* W1  = (const float*)d_in[8];
    const float* b1  = (const float*)d_in[9];
    const float* g1  = (const float*)d_in[10];
    const float* be1 = (const float*)d_in[11];
    const float* W2  = (const float*)d_in[12];
    const float* b2  = (const float*)d_in[13];
    const float* g2  = (const float*)d_in[14];
    const float* be2 = (const float*)d_in[15];
    const float* W3  = (const float*)d_in[16];
    const float* b3  = (const float*)d_in[17];
    float* out = (float*)d_out;

    cudaFuncSetAttribute(mlp_kernel,
                         cudaFuncAttributeMaxDynamicSharedMemorySize, SM1_BYTES);

    species_kernel<<<NSPEC, 64>>>(semb, remb, W1, b1);
    zero_kernel<<<(NNODES + 1023) / 1024, 1024>>>();
    hist_kernel<<<(E_TOTAL + 255) / 256, 256>>>(receivers);
    scan_kernel<<<1, 1024>>>();
    fill_kernel<<<(E_TOTAL + 255) / 256, 256>>>(receivers);
    mlp_kernel<<<E_TOTAL / T1, 256, SM1_BYTES>>>(
        species, dist, senders, receivers,
        W1, g1, be1, W2, b2, g2, be2, W3, b3);
    wigner_gather<<<(NNODES + 7) / 8, 256>>>(wig, env, out);
}

// round 4
// speedup vs baseline: 1.5211x; 1.2159x over previous
#include <cuda_runtime.h>
#include <math.h>

#define E_TOTAL 400000
#define NNODES  12500
#define T1      128     // edges per CTA, kernel 1
#define PH      68      // smem row pitch (floats)
#define FULLC   25
#define MALL    19
#define NSPEC   90

typedef unsigned long long ull;

// scratch (static device globals; no allocation in kernel_launch)
__device__ float F_buf[(size_t)E_TOTAL * 320];   // MLP output per edge
__device__ int   d_cnt[NNODES];
__device__ int   d_cur[NNODES];
__device__ int   d_offs[NNODES + 1];
__device__ int   d_eids[E_TOTAL];
__device__ float SPb[NSPEC * 64];                // semb @ W1[128:192] + b1
__device__ float RPb[NSPEC * 64];                // remb @ W1[192:256]

__device__ __forceinline__ ull pack2(float x) {
    ull r; asm("mov.b64 %0,{%1,%1};" : "=l"(r) : "f"(x)); return r;
}
__device__ __forceinline__ ull pack2xy(float x, float y) {
    ull r; asm("mov.b64 %0,{%1,%2};" : "=l"(r) : "f"(x), "f"(y)); return r;
}
__device__ __forceinline__ void fma2(ull& d, ull a, ull b) {
    asm("fma.rn.f32x2 %0,%1,%2,%0;" : "+l"(d) : "l"(a), "l"(b));
}
__device__ __forceinline__ float2 unpk(ull v) {
    float2 o; asm("mov.b64 {%0,%1},%2;" : "=f"(o.x), "=f"(o.y) : "l"(v)); return o;
}

// permuted float4 slot within a 64-float W row:
// slot j in first half holds original c4=2j (cols 8j..8j+3) -> lane cj reads
// its first 16B at byte k*256 + cj*16 (conflict-free), second at +128.
__device__ __forceinline__ int wperm(int c4) { return ((c4 & 1) << 3) | (c4 >> 1); }

// ---------------------------------------------------------------- CSR build
__global__ void zero_kernel() {
    int i = blockIdx.x * blockDim.x + threadIdx.x;
    if (i < NNODES) { d_cnt[i] = 0; d_cur[i] = 0; }
}
__global__ void hist_kernel(const int* __restrict__ receivers) {
    int e = blockIdx.x * blockDim.x + threadIdx.x;
    if (e < E_TOTAL) atomicAdd(&d_cnt[receivers[e]], 1);
}
__global__ void scan_kernel() {
    __shared__ int s[1024];
    const int CH = (NNODES + 1023) / 1024;   // 13
    int t = threadIdx.x;
    int base = t * CH;
    int loc[CH];
    int sum = 0;
    #pragma unroll
    for (int i = 0; i < CH; ++i) {
        int v = (base + i < NNODES) ? d_cnt[base + i] : 0;
        loc[i] = sum; sum += v;
    }
    s[t] = sum;
    __syncthreads();
    for (int off = 1; off < 1024; off <<= 1) {
        int v = s[t];
        int u = (t >= off) ? s[t - off] : 0;
        __syncthreads();
        s[t] = v + u;
        __syncthreads();
    }
    int excl = (t > 0) ? s[t - 1] : 0;
    #pragma unroll
    for (int i = 0; i < CH; ++i)
        if (base + i < NNODES) d_offs[base + i] = excl + loc[i];
    if (t == 1023) d_offs[NNODES] = s[1023];
}
__global__ void fill_kernel(const int* __restrict__ receivers) {
    int e = blockIdx.x * blockDim.x + threadIdx.x;
    if (e < E_TOTAL) {
        int r = receivers[e];
        int pos = atomicAdd(&d_cur[r], 1);
        d_eids[d_offs[r] + pos] = e;
    }
}

// -------------------------------------------- species projection precompute
__global__ void species_kernel(const float* __restrict__ semb,
                               const float* __restrict__ remb,
                               const float* __restrict__ W1,
                               const float* __restrict__ b1)
{
    int s = blockIdx.x;        // 0..89
    int c = threadIdx.x;       // 0..63
    float sp = b1[c], rp = 0.0f;
    #pragma unroll 8
    for (int k = 0; k < 64; ++k) {
        sp += semb[s * 64 + k] * W1[(128 + k) * 64 + c];
        rp += remb[s * 64 + k] * W1[(192 + k) * 64 + c];
    }
    SPb[s * 64 + c] = sp;
    RPb[s * 64 + c] = rp;
}

// ---------------------------------------------------------------- MLP GEMM
// W in smem is stored PERMUTED (see wperm). b-loads are conflict-free.
__device__ __forceinline__ void gemm64(const float* __restrict__ As,
                                       const ull*  __restrict__ Wp,
                                       int row0, int cj, ull acc[16])
{
    const float* a0 = As + (row0 + 0) * PH;
    const float* a1 = As + (row0 + 1) * PH;
    const float* a2 = As + (row0 + 2) * PH;
    const float* a3 = As + (row0 + 3) * PH;
    #pragma unroll 2
    for (int k4 = 0; k4 < 16; ++k4) {
        float4 v0 = *(const float4*)(a0 + 4 * k4);
        float4 v1 = *(const float4*)(a1 + 4 * k4);
        float4 v2 = *(const float4*)(a2 + 4 * k4);
        float4 v3 = *(const float4*)(a3 + 4 * k4);
        float a0a[4] = {v0.x, v0.y, v0.z, v0.w};
        float a1a[4] = {v1.x, v1.y, v1.z, v1.w};
        float a2a[4] = {v2.x, v2.y, v2.z, v2.w};
        float a3a[4] = {v3.x, v3.y, v3.z, v3.w};
        #pragma unroll
        for (int kk = 0; kk < 4; ++kk) {
            int k = 4 * k4 + kk;
            // first 16B (cols 8cj..8cj+3) and second 16B (cols 8cj+4..8cj+7)
            ulonglong2 bA = *(const ulonglong2*)(Wp + k * 32 + cj * 2);
            ulonglong2 bB = *(const ulonglong2*)(Wp + k * 32 + 16 + cj * 2);
            ull p;
            p = pack2(a0a[kk]); fma2(acc[0], p, bA.x); fma2(acc[1], p, bA.y); fma2(acc[2],  p, bB.x); fma2(acc[3],  p, bB.y);
            p = pack2(a1a[kk]); fma2(acc[4], p, bA.x); fma2(acc[5], p, bA.y); fma2(acc[6],  p, bB.x); fma2(acc[7],  p, bB.y);
            p = pack2(a2a[kk]); fma2(acc[8], p, bA.x); fma2(acc[9], p, bA.y); fma2(acc[10], p, bB.x); fma2(acc[11], p, bB.y);
            p = pack2(a3a[kk]); fma2(acc[12],p, bA.x); fma2(acc[13],p, bA.y); fma2(acc[14], p, bB.x); fma2(acc[15], p, bB.y);
        }
    }
}

__device__ __forceinline__ void store_acc_smem(float* __restrict__ H, int row0, int cj,
                                               const ull acc[16], float4 bl, float4 bh)
{
    #pragma unroll
    for (int r = 0; r < 4; ++r) {
        float2 e0 = unpk(acc[4*r+0]); float2 e1 = unpk(acc[4*r+1]);
        float2 e2 = unpk(acc[4*r+2]); float2 e3 = unpk(acc[4*r+3]);
        float* p = H + (row0 + r) * PH + cj * 8;
        *(float4*)(p)     = make_float4(e0.x + bl.x, e0.y + bl.y, e1.x + bl.z, e1.y + bl.w);
        *(float4*)(p + 4) = make_float4(e2.x + bh.x, e2.y + bh.y, e3.x + bh.z, e3.y + bh.w);
    }
}

__device__ __forceinline__ void ln_silu(float* __restrict__ Bs,
                                        const float* __restrict__ g,
                                        const float* __restrict__ be,
                                        int lane, int warp)
{
    float2 gv = *(const float2*)(g  + 2 * lane);
    float2 bv = *(const float2*)(be + 2 * lane);
    #pragma unroll
    for (int rr = 0; rr < 16; ++rr) {
        int row = warp * 16 + rr;
        float2 v = *(float2*)(Bs + row * PH + 2 * lane);
        float s  = v.x + v.y;
        float s2 = v.x * v.x + v.y * v.y;
        #pragma unroll
        for (int o = 16; o > 0; o >>= 1) {
            s  += __shfl_xor_sync(0xffffffffu, s,  o);
            s2 += __shfl_xor_sync(0xffffffffu, s2, o);
        }
        float mu  = s * (1.0f / 64.0f);
        float var = s2 * (1.0f / 64.0f) - mu * mu;
        float rs  = rsqrtf(fmaxf(var, 0.0f) + 1e-5f);
        float x0 = (v.x - mu) * rs * gv.x + bv.x;
        float x1 = (v.y - mu) * rs * gv.y + bv.y;
        x0 = x0 / (1.0f + __expf(-x0));
        x1 = x1 / (1.0f + __expf(-x1));
        *(float2*)(Bs + row * PH + 2 * lane) = make_float2(x0, x1);
    }
}

#define SM1_FLOATS (T1 * PH + T1 * PH + 64 * 64 + 64)
#define SM1_BYTES  (SM1_FLOATS * 4 + 1024)

__global__ __launch_bounds__(256, 2)
void mlp_kernel(const int*   __restrict__ species,
                const float* __restrict__ dist,
                const int*   __restrict__ senders,
                const int*   __restrict__ receivers,
                const float* __restrict__ W1,
                const float* __restrict__ g1, const float* __restrict__ be1,
                const float* __restrict__ W2, const float* __restrict__ b2,
                const float* __restrict__ g2, const float* __restrict__ be2,
                const float* __restrict__ W3, const float* __restrict__ b3)
{
    extern __shared__ float sm[];
    float* Xc = sm;                     // aliased as H2 later
    float* H1 = Xc + T1 * PH;
    float* Ws = H1 + T1 * PH;
    int*   spS = (int*)(Ws + 64 * 64 + 64);
    int*   spR = spS + T1;

    const int tid  = threadIdx.x;
    const int lane = tid & 31;
    const int warp = tid >> 5;
    const int ri   = tid >> 3;
    const int cj   = tid & 7;
    const int row0 = 4 * ri;
    const int base = blockIdx.x * T1;

    if (tid < T1) {
        spS[tid] = species[senders[base + tid]];
        spR[tid] = species[receivers[base + tid]];
    }
    __syncthreads();

    // ---- stage 1 acc init from precomputed species projections (incl. b1)
    ull acc[16];
    #pragma unroll
    for (int r = 0; r < 4; ++r) {
        int row = row0 + r;
        int ss = spS[row], sr = spR[row];
        float4 u0 = ((const float4*)SPb)[ss * 16 + cj * 2];
        float4 u1 = ((const float4*)SPb)[ss * 16 + cj * 2 + 1];
        float4 v0 = ((const float4*)RPb)[sr * 16 + cj * 2];
        float4 v1 = ((const float4*)RPb)[sr * 16 + cj * 2 + 1];
        acc[4*r+0] = pack2xy(u0.x + v0.x, u0.y + v0.y);
        acc[4*r+1] = pack2xy(u0.z + v0.z, u0.w + v0.w);
        acc[4*r+2] = pack2xy(u1.x + v1.x, u1.y + v1.y);
        acc[4*r+3] = pack2xy(u1.z + v1.z, u1.w + v1.w);
    }

    // ---- stage 1: += dist @ W1[0:128] (2 chunks of 64)
    for (int kc = 0; kc < 2; ++kc) {
        __syncthreads();
        #pragma unroll
        for (int q = 0; q < 4; ++q) {
            int lin = tid + 256 * q;
            int k = lin >> 4, c4 = lin & 15;
            ((float4*)Ws)[k * 16 + wperm(c4)] = ((const float4*)W1)[(kc * 64 + k) * 16 + c4];
        }
        #pragma unroll
        for (int q = 0; q < 8; ++q) {
            int lin = tid + 256 * q;
            int row = lin >> 4, c4 = lin & 15;
            float4 v = ((const float4*)dist)[(size_t)(base + row) * 32 + kc * 16 + c4];
            *(float4*)(Xc + row * PH + c4 * 4) = v;
        }
        __syncthreads();
        gemm64(Xc, (const ull*)Ws, row0, cj, acc);
    }
    {
        float4 z = make_float4(0, 0, 0, 0);
        __syncthreads();
        store_acc_smem(H1, row0, cj, acc, z, z);
    }
    __syncthreads();
    ln_silu(H1, g1, be1, lane, warp);
    __syncthreads();

    // ---- stage 2: H2 = H1 @ W2 (H2 aliases Xc)
    #pragma unroll
    for (int q = 0; q < 4; ++q) {
        int lin = tid + 256 * q;
        int k = lin >> 4, c4 = lin & 15;
        ((float4*)Ws)[k * 16 + wperm(c4)] = ((const float4*)W2)[lin];
    }
    __syncthreads();
    #pragma unroll
    for (int i = 0; i < 16; ++i) acc[i] = 0ull;
    gemm64(H1, (const ull*)Ws, row0, cj, acc);
    {
        float4 bl = ((const float4*)b2)[cj * 2];
        float4 bh = ((const float4*)b2)[cj * 2 + 1];
        __syncthreads();
        store_acc_smem(Xc, row0, cj, acc, bl, bh);
    }
    __syncthreads();
    ln_silu(Xc, g2, be2, lane, warp);

    // ---- stage 3: F_m = H2 @ W3[:, 64m:64m+64] + b3 -> F_buf
    for (int m = 0; m < 5; ++m) {
        __syncthreads();
        #pragma unroll
        for (int q = 0; q < 4; ++q) {
            int lin = tid + 256 * q;
            int k = lin >> 4, c4 = lin & 15;
            ((float4*)Ws)[k * 16 + wperm(c4)] = ((const float4*)W3)[k * 80 + m * 16 + c4];
        }
        __syncthreads();
        #pragma unroll
        for (int i = 0; i < 16; ++i) acc[i] = 0ull;
        gemm64(Xc, (const ull*)Ws, row0, cj, acc);

        float4 bl = ((const float4*)b3)[m * 16 + cj * 2];
        float4 bh = ((const float4*)b3)[m * 16 + cj * 2 + 1];
        #pragma unroll
        for (int r = 0; r < 4; ++r) {
            float2 e0 = unpk(acc[4*r+0]); float2 e1 = unpk(acc[4*r+1]);
            float2 e2 = unpk(acc[4*r+2]); float2 e3 = unpk(acc[4*r+3]);
            float* p = F_buf + (size_t)(base + row0 + r) * 320 + m * 64 + cj * 8;
            *(float4*)(p)     = make_float4(e0.x + bl.x, e0.y + bl.y, e1.x + bl.z, e1.y + bl.w);
            *(float4*)(p + 4) = make_float4(e2.x + bh.x, e2.y + bh.y, e3.x + bh.z, e3.y + bh.w);
        }
    }
}

// --------------------------------- kernel 2: gather per node, no atomics
__global__ __launch_bounds__(256)
void wigner_gather(const float* __restrict__ wig,
                   const float* __restrict__ env,
                   float* __restrict__ out)
{
    __shared__ ull wbp[8][25 * 8];     // per-warp packed coeffs, stride 8 per f
    const int tid  = threadIdx.x;
    const int lane = tid & 31;
    const int warp = tid >> 5;
    const int node = blockIdx.x * 8 + warp;
    if (node >= NNODES) return;

    ull acc[FULLC];
    #pragma unroll
    for (int f = 0; f < FULLC; ++f) acc[f] = 0ull;

    const int beg = d_offs[node];
    const int end = d_offs[node + 1];
    ull* wp = wbp[warp];

    for (int idx = beg; idx < end; ++idx) {
        int e = d_eids[idx];
        float sc = env[e] * 0.2f;      // fold 1/RESCALE
        const float* wr = wig + (size_t)e * (FULLC * MALL);
        #pragma unroll
        for (int t = 0; t < 4; ++t) {
            int lin = lane + 32 * t;
            if (lin < 125) {
                int f = lin / 5;
                int m = lin - 5 * f;
                wp[f * 8 + m] = pack2(wr[f * MALL + m] * sc);
            }
        }
        __syncwarp();

        const ull* fp = (const ull*)(F_buf + (size_t)e * 320 + 2 * lane);
        ull fm0 = fp[0], fm1 = fp[32], fm2 = fp[64], fm3 = fp[96], fm4 = fp[128];

        #pragma unroll
        for (int f = 0; f < FULLC; ++f) {
            ulonglong2 wA = *(const ulonglong2*)(wp + f * 8);
            ulonglong2 wB = *(const ulonglong2*)(wp + f * 8 + 2);
            ull w4 = wp[f * 8 + 4];
            ull r = acc[f];
            fma2(r, wA.x, fm0);
            fma2(r, wA.y, fm1);
            fma2(r, wB.x, fm2);
            fma2(r, wB.y, fm3);
            fma2(r, w4,   fm4);
            acc[f] = r;
        }
        __syncwarp();
    }

    float* ob = out + (size_t)node * 1600 + 2 * lane;
    #pragma unroll
    for (int f = 0; f < FULLC; ++f) {
        float2 rv = unpk(acc[f]);
        *(float2*)(ob + f * 64) = rv;
    }
}

extern "C" void kernel_launch(void* const* d_in, const int* in_sizes, int n_in,
                              void* d_out, int out_size)
{
    const int*   species   = (const int*)  d_in[0];
    const float* dist      = (const float*)d_in[1];
    const int*   senders   = (const int*)  d_in[2];
    const int*   receivers = (const int*)  d_in[3];
    const float* wig       = (const float*)d_in[4];
    const float* env       = (const float*)d_in[5];
    const float* semb      = (const float*)d_in[6];
    const float* remb      = (const float*)d_in[7];
    const float* W1  = (const float*)d_in[8];
    const float* b1  = (const float*)d_in[9];
    const float* g1  = (const float*)d_in[10];
    const float* be1 = (const float*)d_in[11];
    const float* W2  = (const float*)d_in[12];
    const float* b2  = (const float*)d_in[13];
    const float* g2  = (const float*)d_in[14];
    const float* be2 = (const float*)d_in[15];
    const float* W3  = (const float*)d_in[16];
    const float* b3  = (const float*)d_in[17];
    float* out = (float*)d_out;

    cudaFuncSetAttribute(mlp_kernel,
                         cudaFuncAttributeMaxDynamicSharedMemorySize, SM1_BYTES);

    species_kernel<<<NSPEC, 64>>>(semb, remb, W1, b1);
    zero_kernel<<<(NNODES + 1023) / 1024, 1024>>>();
    hist_kernel<<<(E_TOTAL + 255) / 256, 256>>>(receivers);
    scan_kernel<<<1, 1024>>>();
    fill_kernel<<<(E_TOTAL + 255) / 256, 256>>>(receivers);
    mlp_kernel<<<E_TOTAL / T1, 256, SM1_BYTES>>>(
        species, dist, senders, receivers,
        W1, g1, be1, W2, b2, g2, be2, W3, b3);
    wigner_gather<<<(NNODES + 7) / 8, 256>>>(wig, env, out);
}